// round 5
// baseline (speedup 1.0000x reference)
#include <cuda_runtime.h>
#include <cuda_bf16.h>

// Single fused kernel, warp-parallel prologue:
//   warps 0..3 each own one QSP chain (x1, x2, t1, t2):
//     lanes 0..len-1: sincos(p/2); shfl-gather; all lanes run the tiny
//     fully-unrolled symbolic chain; lane 0 writes its DISJOINT coefficient
//     slots (len-3 chains -> e0,e2,f1 ; len-4 chains -> e1,e3,f0,f2).
//   One __syncthreads, then every thread evaluates
//     A(z) = P3(z) + sqrt(1-z^2)*Q2(z)  per block, out = Re[A_x * A_t]/16.
//
// smem coefficient layout (28 floats):
//   x-block base 0:  [0..3] e_r, [4..7] e_i, [8..10] f_r, [11..13] f_i
//   t-block base 14: same layout.

// v = RZ(p_{N-1}) S ... S RZ(p_0) (1,1)^T, symbolic in (z, s):
// coeff index j = power of s. out[j] = v0[j] + v1[j]. Fully unrolled.
template <int N>
__device__ __forceinline__ void chain_coeffs_T(const float2* cs, float2* out) {
    float2 v0[N], v1[N];
    v0[0] = make_float2(cs[0].x, -cs[0].y);
    v1[0] = make_float2(cs[0].x,  cs[0].y);
#pragma unroll
    for (int k = 1; k < N; k++) {
        float2 n0[N], n1[N];
#pragma unroll
        for (int j = 0; j <= k; j++) {
            n0[j] = make_float2(0.f, 0.f);
            n1[j] = make_float2(0.f, 0.f);
        }
#pragma unroll
        for (int j = 0; j < k; j++) {
            n0[j].x += v0[j].x; n0[j].y += v0[j].y;
            n1[j].x += v1[j].x; n1[j].y += v1[j].y;
            n0[j + 1].x += -v1[j].y; n0[j + 1].y += v1[j].x;
            n1[j + 1].x += -v0[j].y; n1[j + 1].y += v0[j].x;
        }
        float c = cs[k].x, s = cs[k].y;
#pragma unroll
        for (int j = 0; j <= k; j++) {
            v0[j] = make_float2(n0[j].x * c + n0[j].y * s, n0[j].y * c - n0[j].x * s);
            v1[j] = make_float2(n1[j].x * c - n1[j].y * s, n1[j].y * c + n1[j].x * s);
        }
    }
#pragma unroll
    for (int j = 0; j < N; j++)
        out[j] = make_float2(v0[j].x + v1[j].x, v0[j].y + v1[j].y);
}

// A = P(z) + s*Q(z): P cubic, Q quadratic, Horner.
__device__ __forceinline__ void eval_block(float z, float s, const float* cf,
                                           float& Ar, float& Ai) {
    float pr = fmaf(cf[3], z, cf[2]);
    pr = fmaf(pr, z, cf[1]);
    pr = fmaf(pr, z, cf[0]);
    float pi = fmaf(cf[7], z, cf[6]);
    pi = fmaf(pi, z, cf[5]);
    pi = fmaf(pi, z, cf[4]);
    float qr = fmaf(cf[10], z, cf[9]);
    qr = fmaf(qr, z, cf[8]);
    float qi = fmaf(cf[13], z, cf[12]);
    qi = fmaf(qi, z, cf[11]);
    Ar = fmaf(s, qr, pr);
    Ai = fmaf(s, qi, pi);
}

__device__ __forceinline__ float eval_one(float t, float x, const float* cf) {
    float sx = sqrtf(fmaxf(fmaf(-x, x, 1.0f), 0.0f));
    float st = sqrtf(fmaxf(fmaf(-t, t, 1.0f), 0.0f));
    float Axr, Axi, Atr, Ati;
    eval_block(x, sx, cf, Axr, Axi);
    eval_block(t, st, cf + 14, Atr, Ati);
    return fmaf(Axr, Atr, -Axi * Ati);
}

__global__ void __launch_bounds__(256)
qpinn_fused(const float* __restrict__ t, const float* __restrict__ x,
            const float* __restrict__ ph_x1, const float* __restrict__ ph_x2,
            const float* __restrict__ ph_t1, const float* __restrict__ ph_t2,
            float* __restrict__ out, int n) {
    __shared__ float s_cf[28];

    // ---- 1. issue input loads first: prologue hides under DRAM latency ----
    int n2 = n >> 1;
    int i = blockIdx.x * blockDim.x + threadIdx.x;
    float2 tv = make_float2(0.f, 0.f), xv = make_float2(0.f, 0.f);
    if (i < n2) {
        tv = reinterpret_cast<const float2*>(t)[i];
        xv = reinterpret_cast<const float2*>(x)[i];
    }

    // ---- 2. warp-parallel chain -> coefficients (warps 0..3) ----
    int w = threadIdx.x >> 5;
    int lane = threadIdx.x & 31;
    if (w < 4) {
        const float* ph = (w == 0) ? ph_x1 : (w == 1) ? ph_x2
                        : (w == 2) ? ph_t1 : ph_t2;
        int len = (w & 1) ? 4 : 3;
        float c = 0.f, s = 0.f;
        if (lane < len) {
            float p = ph[lane];
            sincosf(0.5f * p, &s, &c);
        }
        float2 cs[4];
#pragma unroll
        for (int k = 0; k < 4; k++) {
            cs[k].x = __shfl_sync(0xffffffffu, c, k);
            cs[k].y = __shfl_sync(0xffffffffu, s, k);
        }
        float scale = (w < 2) ? 0.0625f : 1.0f;   // fold global 1/16 into x-block
        float* base = s_cf + ((w < 2) ? 0 : 14);
        if ((w & 1) == 0) {
            // degree-2 chain: o0 z^2 + o1 z s + o2 s^2
            //   = o2 + (o0-o2) z^2 + s*(o1 z)  -> e0, e2, f1
            float2 o[3];
            chain_coeffs_T<3>(cs, o);
            if (lane == 0) {
                base[0]  = o[2].x * scale;            base[4]  = o[2].y * scale;
                base[2]  = (o[0].x - o[2].x) * scale; base[6]  = (o[0].y - o[2].y) * scale;
                base[9]  = o[1].x * scale;            base[12] = o[1].y * scale;
            }
        } else {
            // degree-3 chain: o0 z^3 + o1 z^2 s + o2 z s^2 + o3 s^3
            //   = o2 z + (o0-o2) z^3 + s*(o3 + (o1-o3) z^2)  -> e1, e3, f0, f2
            float2 o[4];
            chain_coeffs_T<4>(cs, o);
            if (lane == 0) {
                base[1]  = o[2].x * scale;            base[5]  = o[2].y * scale;
                base[3]  = (o[0].x - o[2].x) * scale; base[7]  = (o[0].y - o[2].y) * scale;
                base[8]  = o[3].x * scale;            base[11] = o[3].y * scale;
                base[10] = (o[1].x - o[3].x) * scale; base[13] = (o[1].y - o[3].y) * scale;
            }
        }
    }
    __syncthreads();

    // ---- 3. evaluate (coefficients broadcast from smem -> regs) ----
    float cf[28];
#pragma unroll
    for (int j = 0; j < 28; j++) cf[j] = s_cf[j];

    if (i < n2) {
        float2 o;
        o.x = eval_one(tv.x, xv.x, cf);
        o.y = eval_one(tv.y, xv.y, cf);
        reinterpret_cast<float2*>(out)[i] = o;
    }
    // tail for odd n (empty for BATCH=262144)
    if (i == 0 && (n & 1)) out[n - 1] = eval_one(t[n - 1], x[n - 1], cf);
}

extern "C" void kernel_launch(void* const* d_in, const int* in_sizes, int n_in,
                              void* d_out, int out_size) {
    const float* t     = (const float*)d_in[0];
    const float* x     = (const float*)d_in[1];
    const float* ph_x1 = (const float*)d_in[2];
    const float* ph_x2 = (const float*)d_in[3];
    const float* ph_t1 = (const float*)d_in[4];
    const float* ph_t2 = (const float*)d_in[5];
    float* out = (float*)d_out;
    int n = in_sizes[0];

    int n2 = n >> 1;
    int blocks = (n2 + 255) / 256;
    if (blocks < 1) blocks = 1;
    qpinn_fused<<<blocks, 256>>>(t, x, ph_x1, ph_x2, ph_t1, ph_t2, out, n);
}

// round 6
// speedup vs baseline: 1.1082x; 1.1082x over previous
#include <cuda_runtime.h>
#include <cuda_bf16.h>

// Single fused kernel, warp-parallel prologue:
//   warps 0..3 each own one QSP chain (x1, x2, t1, t2):
//     lanes 0..len-1: __sincosf(p/2); shfl-gather; all lanes run the tiny
//     fully-unrolled symbolic chain; lane 0 writes its DISJOINT coefficient
//     slots (len-3 chains -> e0,e2,f1 ; len-4 chains -> e1,e3,f0,f2).
//   One __syncthreads, then every thread evaluates 4 elements:
//     A(z) = P3(z) + sqrt(1-z^2)*Q2(z)  per block, out = Re[A_x * A_t]/16.
//
// smem coefficient layout (28 floats):
//   x-block base 0:  [0..3] e_r, [4..7] e_i, [8..10] f_r, [11..13] f_i
//   t-block base 14: same layout.

// v = RZ(p_{N-1}) S ... S RZ(p_0) (1,1)^T, symbolic in (z, s):
// coeff index j = power of s. out[j] = v0[j] + v1[j]. Fully unrolled.
template <int N>
__device__ __forceinline__ void chain_coeffs_T(const float2* cs, float2* out) {
    float2 v0[N], v1[N];
    v0[0] = make_float2(cs[0].x, -cs[0].y);
    v1[0] = make_float2(cs[0].x,  cs[0].y);
#pragma unroll
    for (int k = 1; k < N; k++) {
        float2 n0[N], n1[N];
#pragma unroll
        for (int j = 0; j <= k; j++) {
            n0[j] = make_float2(0.f, 0.f);
            n1[j] = make_float2(0.f, 0.f);
        }
#pragma unroll
        for (int j = 0; j < k; j++) {
            n0[j].x += v0[j].x; n0[j].y += v0[j].y;
            n1[j].x += v1[j].x; n1[j].y += v1[j].y;
            n0[j + 1].x += -v1[j].y; n0[j + 1].y += v1[j].x;
            n1[j + 1].x += -v0[j].y; n1[j + 1].y += v0[j].x;
        }
        float c = cs[k].x, s = cs[k].y;
#pragma unroll
        for (int j = 0; j <= k; j++) {
            v0[j] = make_float2(n0[j].x * c + n0[j].y * s, n0[j].y * c - n0[j].x * s);
            v1[j] = make_float2(n1[j].x * c - n1[j].y * s, n1[j].y * c + n1[j].x * s);
        }
    }
#pragma unroll
    for (int j = 0; j < N; j++)
        out[j] = make_float2(v0[j].x + v1[j].x, v0[j].y + v1[j].y);
}

// A = P(z) + s*Q(z): P cubic, Q quadratic, Horner.
__device__ __forceinline__ void eval_block(float z, float s, const float* cf,
                                           float& Ar, float& Ai) {
    float pr = fmaf(cf[3], z, cf[2]);
    pr = fmaf(pr, z, cf[1]);
    pr = fmaf(pr, z, cf[0]);
    float pi = fmaf(cf[7], z, cf[6]);
    pi = fmaf(pi, z, cf[5]);
    pi = fmaf(pi, z, cf[4]);
    float qr = fmaf(cf[10], z, cf[9]);
    qr = fmaf(qr, z, cf[8]);
    float qi = fmaf(cf[13], z, cf[12]);
    qi = fmaf(qi, z, cf[11]);
    Ar = fmaf(s, qr, pr);
    Ai = fmaf(s, qi, pi);
}

__device__ __forceinline__ float eval_one(float t, float x, const float* cf) {
    float sx = sqrtf(fmaxf(fmaf(-x, x, 1.0f), 0.0f));
    float st = sqrtf(fmaxf(fmaf(-t, t, 1.0f), 0.0f));
    float Axr, Axi, Atr, Ati;
    eval_block(x, sx, cf, Axr, Axi);
    eval_block(t, st, cf + 14, Atr, Ati);
    return fmaf(Axr, Atr, -Axi * Ati);
}

__global__ void __launch_bounds__(256)
qpinn_fused(const float* __restrict__ t, const float* __restrict__ x,
            const float* __restrict__ ph_x1, const float* __restrict__ ph_x2,
            const float* __restrict__ ph_t1, const float* __restrict__ ph_t2,
            float* __restrict__ out, int n) {
    __shared__ float s_cf[28];

    // ---- 1. issue input loads first: prologue hides under DRAM latency ----
    int n4 = n >> 2;
    int i = blockIdx.x * blockDim.x + threadIdx.x;
    float4 tv = make_float4(0.f, 0.f, 0.f, 0.f);
    float4 xv = make_float4(0.f, 0.f, 0.f, 0.f);
    if (i < n4) {
        tv = reinterpret_cast<const float4*>(t)[i];
        xv = reinterpret_cast<const float4*>(x)[i];
    }

    // ---- 2. warp-parallel chain -> coefficients (warps 0..3) ----
    int w = threadIdx.x >> 5;
    int lane = threadIdx.x & 31;
    if (w < 4) {
        const float* ph = (w == 0) ? ph_x1 : (w == 1) ? ph_x2
                        : (w == 2) ? ph_t1 : ph_t2;
        int len = (w & 1) ? 4 : 3;
        float c = 0.f, s = 0.f;
        if (lane < len) {
            float p = ph[lane];
            __sincosf(0.5f * p, &s, &c);   // p/2 in [0, pi]: fast path is exact enough
        }
        float2 cs[4];
#pragma unroll
        for (int k = 0; k < 4; k++) {
            cs[k].x = __shfl_sync(0xffffffffu, c, k);
            cs[k].y = __shfl_sync(0xffffffffu, s, k);
        }
        float scale = (w < 2) ? 0.0625f : 1.0f;   // fold global 1/16 into x-block
        float* base = s_cf + ((w < 2) ? 0 : 14);
        if ((w & 1) == 0) {
            // degree-2 chain: o0 z^2 + o1 z s + o2 s^2
            //   = o2 + (o0-o2) z^2 + s*(o1 z)  -> e0, e2, f1
            float2 o[3];
            chain_coeffs_T<3>(cs, o);
            if (lane == 0) {
                base[0]  = o[2].x * scale;            base[4]  = o[2].y * scale;
                base[2]  = (o[0].x - o[2].x) * scale; base[6]  = (o[0].y - o[2].y) * scale;
                base[9]  = o[1].x * scale;            base[12] = o[1].y * scale;
            }
        } else {
            // degree-3 chain: o0 z^3 + o1 z^2 s + o2 z s^2 + o3 s^3
            //   = o2 z + (o0-o2) z^3 + s*(o3 + (o1-o3) z^2)  -> e1, e3, f0, f2
            float2 o[4];
            chain_coeffs_T<4>(cs, o);
            if (lane == 0) {
                base[1]  = o[2].x * scale;            base[5]  = o[2].y * scale;
                base[3]  = (o[0].x - o[2].x) * scale; base[7]  = (o[0].y - o[2].y) * scale;
                base[8]  = o[3].x * scale;            base[11] = o[3].y * scale;
                base[10] = (o[1].x - o[3].x) * scale; base[13] = (o[1].y - o[3].y) * scale;
            }
        }
    }
    __syncthreads();

    // ---- 3. evaluate (coefficients broadcast from smem -> regs) ----
    float cf[28];
#pragma unroll
    for (int j = 0; j < 28; j++) cf[j] = s_cf[j];

    if (i < n4) {
        float4 o;
        o.x = eval_one(tv.x, xv.x, cf);
        o.y = eval_one(tv.y, xv.y, cf);
        o.z = eval_one(tv.z, xv.z, cf);
        o.w = eval_one(tv.w, xv.w, cf);
        reinterpret_cast<float4*>(out)[i] = o;
    }
    // tail for n % 4 != 0 (empty for BATCH=262144)
    if (i == 0) {
        for (int j = n4 << 2; j < n; j++) out[j] = eval_one(t[j], x[j], cf);
    }
}

extern "C" void kernel_launch(void* const* d_in, const int* in_sizes, int n_in,
                              void* d_out, int out_size) {
    const float* t     = (const float*)d_in[0];
    const float* x     = (const float*)d_in[1];
    const float* ph_x1 = (const float*)d_in[2];
    const float* ph_x2 = (const float*)d_in[3];
    const float* ph_t1 = (const float*)d_in[4];
    const float* ph_t2 = (const float*)d_in[5];
    float* out = (float*)d_out;
    int n = in_sizes[0];

    int n4 = n >> 2;
    int blocks = (n4 + 255) / 256;
    if (blocks < 1) blocks = 1;
    qpinn_fused<<<blocks, 256>>>(t, x, ph_x1, ph_x2, ph_t1, ph_t2, out, n);
}